// round 3
// baseline (speedup 1.0000x reference)
#include <cuda_runtime.h>
#include <cuda_bf16.h>

#define B_ 8
#define H_ 12
#define N_ 577
#define HD_ 64
#define BH_ (B_*H_)           // 96
#define NTOK (BH_*N_)         // 55392
#define NN_ ((size_t)N_*N_)   // 332929

// Per-token quadratic-form coefficients: a0 = -0.5*inv00, a1 = -inv01, a2 = -0.5*inv11
__device__ float g_coef[NTOK * 3];

// ---------------------------------------------------------------------------
// Kernel 1: sigma MLP -> covariance inverse coefficients.
// One thread per token; W1/W2/b in shared memory; hidden kept in registers.
// ---------------------------------------------------------------------------
__global__ __launch_bounds__(128) void mlp_kernel(
    const float* __restrict__ q,
    const float* __restrict__ W1,
    const float* __restrict__ b1,
    const float* __restrict__ W2,
    const float* __restrict__ b2)
{
    __shared__ float4 w1s[64 * 16];   // [k][j4] : W1 row-major as float4 over j
    __shared__ float  b1s[64];
    __shared__ float  w2s[64 * 3];
    __shared__ float  b2s[3];

    const int tid = threadIdx.x;
    for (int idx = tid; idx < 1024; idx += 128) w1s[idx] = ((const float4*)W1)[idx];
    for (int idx = tid; idx < 64;   idx += 128) b1s[idx] = b1[idx];
    for (int idx = tid; idx < 192;  idx += 128) w2s[idx] = W2[idx];
    if (tid < 3) b2s[tid] = b2[tid];
    __syncthreads();

    const int token = blockIdx.x * 128 + tid;
    if (token >= NTOK) return;

    const float4* q4 = (const float4*)(q + (size_t)token * HD_);

    float h[64];
    #pragma unroll
    for (int j = 0; j < 64; j++) h[j] = b1s[j];

    for (int k4 = 0; k4 < 16; k4++) {
        float4 qv = q4[k4];
        float qk[4] = {qv.x, qv.y, qv.z, qv.w};
        #pragma unroll
        for (int kk = 0; kk < 4; kk++) {
            const float qc = qk[kk];
            const int krow = (k4 * 4 + kk) * 16;
            #pragma unroll
            for (int j4 = 0; j4 < 16; j4++) {
                float4 w = w1s[krow + j4];
                h[4*j4+0] = fmaf(qc, w.x, h[4*j4+0]);
                h[4*j4+1] = fmaf(qc, w.y, h[4*j4+1]);
                h[4*j4+2] = fmaf(qc, w.z, h[4*j4+2]);
                h[4*j4+3] = fmaf(qc, w.w, h[4*j4+3]);
            }
        }
    }

    float s0 = b2s[0], s1 = b2s[1], s2 = b2s[2];
    #pragma unroll 8
    for (int j = 0; j < 64; j++) {
        float x = h[j];
        // exact gelu: x * 0.5 * (1 + erf(x / sqrt(2)))
        float g = 0.5f * x * (1.0f + erff(x * 0.70710678118654752f));
        s0 = fmaf(g, w2s[j*3+0], s0);
        s1 = fmaf(g, w2s[j*3+1], s1);
        s2 = fmaf(g, w2s[j*3+2], s2);
    }

    float sx  = fmaxf(s0, 0.0f) + 1.0f;
    float sy  = fmaxf(s1, 0.0f) + 1.0f;
    float rho = 0.99f * tanhf(s2);
    float sxx = sx * sx;
    float syy = sy * sy;
    float sxy = rho * sx * sy;
    float det = sxx * syy - sxy * sxy;   // > 0 always (rho^2 < 0.9801)
    float rdet = 1.0f / det;

    // w = -0.5*(inv00*dx^2 + 2*inv01*dx*dy + inv11*dy^2)
    g_coef[token*3 + 0] = -0.5f * (syy * rdet);
    g_coef[token*3 + 1] =          sxy * rdet;    // = -inv01
    g_coef[token*3 + 2] = -0.5f * (sxx * rdet);
}

// ---------------------------------------------------------------------------
// Kernel 2: elementwise mask.
// Row-max is exactly 1.0 (PD quadratic form => w<=0; CLS col gives w=0 in every
// row), so probs = clip(exp(w), EPS, 1-EPS) with no reduction.
// mask = sigmoid((logits+noise)/0.1) = 1 / (1 + r^10),
//        r = (1-p)(1-u) / (p*u).
// Thread owns one (i,j): dists loaded ONCE, reused across all 96 (b,h).
// ---------------------------------------------------------------------------
__global__ __launch_bounds__(128) void mask_kernel(
    const float* __restrict__ u,
    const float* __restrict__ dists,
    float* __restrict__ out)
{
    __shared__ float cs[BH_ * 3];

    const int tid = threadIdx.x;
    const int i = blockIdx.y;
    const int j = blockIdx.x * 128 + tid;

    // stage this row's coefficients for all 96 (b,h)
    for (int idx = tid; idx < BH_ * 3; idx += 128) {
        int bh = idx / 3, m = idx - bh * 3;
        cs[idx] = g_coef[((size_t)bh * N_ + i) * 3 + m];
    }
    __syncthreads();

    if (j >= N_) return;

    const float2 d = ((const float2*)dists)[(size_t)i * N_ + j];
    const float xx = d.x * d.x;
    const float xy = d.x * d.y;
    const float yy = d.y * d.y;

    const float EPS  = (float)1e-6;
    const float OMEPS = (float)(1.0 - 1e-6);

    const size_t base = (size_t)i * N_ + j;

    #pragma unroll 4
    for (int bh = 0; bh < BH_; bh++) {
        const float a0 = cs[bh*3+0];
        const float a1 = cs[bh*3+1];
        const float a2 = cs[bh*3+2];
        const size_t off = (size_t)bh * NN_ + base;

        const float uu = __ldcs(u + off);

        float w = fmaf(a0, xx, fmaf(a1, xy, a2 * yy));
        float p = __expf(w);
        p = fminf(fmaxf(p, EPS), OMEPS);

        // r = ((1-p)(1-u)) / (p*u);  mask = 1/(1+r^10)
        float num = (1.0f - p) * (1.0f - uu);
        float den = p * uu;
        float r  = __fdividef(num, den);
        float r2 = r * r;
        float r4 = r2 * r2;
        float r5 = r4 * r;
        float r10 = r5 * r5;              // inf -> mask 0; 0 -> mask 1 (matches ref saturation)
        float mask = __fdividef(1.0f, 1.0f + r10);

        __stcs(out + off, mask);
    }
}

extern "C" void kernel_launch(void* const* d_in, const int* in_sizes, int n_in,
                              void* d_out, int out_size)
{
    const float* query = (const float*)d_in[0];
    const float* W1    = (const float*)d_in[1];
    const float* b1    = (const float*)d_in[2];
    const float* W2    = (const float*)d_in[3];
    const float* b2    = (const float*)d_in[4];
    const float* u     = (const float*)d_in[5];
    const float* dists = (const float*)d_in[6];
    float* out = (float*)d_out;

    mlp_kernel<<<(NTOK + 127) / 128, 128>>>(query, W1, b1, W2, b2);

    dim3 grid((N_ + 127) / 128, N_);   // 5 x 577
    mask_kernel<<<grid, 128>>>(u, dists, out);
}

// round 4
// speedup vs baseline: 1.5916x; 1.5916x over previous
#include <cuda_runtime.h>
#include <cuda_bf16.h>

#define B_ 8
#define H_ 12
#define N_ 577
#define HD_ 64
#define BH_ (B_*H_)            // 96
#define NTOK (BH_*N_)          // 55392
#define NNU  332929u           // N*N
#define TOTAL (96u * 332929u)  // 31,961,184 (divisible by 4)
#define TOTAL4 (TOTAL / 4u)    // 7,990,296

// Per-token quadratic-form coefficients (w = c.x*dx^2 + c.y*dx*dy + c.z*dy^2), padded to float4
__device__ float4 g_coef4[NTOK];

// ---------------------------------------------------------------------------
// Kernel 1: sigma MLP. Two threads per token, each owns 32 hidden units,
// pair-reduced via shfl_xor. 256-thread blocks -> ~60 regs/thread, high occ.
// ---------------------------------------------------------------------------
__global__ __launch_bounds__(256) void mlp_kernel(
    const float* __restrict__ q,
    const float* __restrict__ W1,
    const float* __restrict__ b1,
    const float* __restrict__ W2,
    const float* __restrict__ b2)
{
    __shared__ float4 w1s[64 * 16];   // [k][j4]
    __shared__ float  b1s[64];
    __shared__ float  w2s[64 * 3];
    __shared__ float  b2s[3];

    const int tid = threadIdx.x;
    for (int idx = tid; idx < 1024; idx += 256) w1s[idx] = ((const float4*)W1)[idx];
    if (tid < 64)  b1s[tid] = b1[tid];
    if (tid < 192) w2s[tid] = W2[tid];
    if (tid < 3)   b2s[tid] = b2[tid];
    __syncthreads();

    int token = blockIdx.x * 128 + (tid >> 1);
    if (token >= NTOK) token = NTOK - 1;       // duplicate-write same value: benign
    const int half = tid & 1;                   // which 32 hidden units

    const float4* q4 = (const float4*)(q + (size_t)token * HD_);

    float h[32];
    #pragma unroll
    for (int j = 0; j < 32; j++) h[j] = b1s[half * 32 + j];

    const int jbase = half * 8;                 // float4 offset into 16-wide row
    #pragma unroll 4
    for (int k4 = 0; k4 < 16; k4++) {
        float4 qv = q4[k4];
        float qk[4] = {qv.x, qv.y, qv.z, qv.w};
        #pragma unroll
        for (int kk = 0; kk < 4; kk++) {
            const float qc = qk[kk];
            const int krow = (k4 * 4 + kk) * 16 + jbase;
            #pragma unroll
            for (int j4 = 0; j4 < 8; j4++) {
                float4 w = w1s[krow + j4];
                h[4*j4+0] = fmaf(qc, w.x, h[4*j4+0]);
                h[4*j4+1] = fmaf(qc, w.y, h[4*j4+1]);
                h[4*j4+2] = fmaf(qc, w.z, h[4*j4+2]);
                h[4*j4+3] = fmaf(qc, w.w, h[4*j4+3]);
            }
        }
    }

    float s0 = 0.f, s1 = 0.f, s2 = 0.f;
    #pragma unroll 8
    for (int j = 0; j < 32; j++) {
        float x = h[j];
        float g = 0.5f * x * (1.0f + erff(x * 0.70710678118654752f));  // exact gelu
        const int jg = (half * 32 + j) * 3;
        s0 = fmaf(g, w2s[jg+0], s0);
        s1 = fmaf(g, w2s[jg+1], s1);
        s2 = fmaf(g, w2s[jg+2], s2);
    }
    // pair reduction (lanes differ only in bit 0; all lanes active)
    s0 += __shfl_xor_sync(0xffffffffu, s0, 1);
    s1 += __shfl_xor_sync(0xffffffffu, s1, 1);
    s2 += __shfl_xor_sync(0xffffffffu, s2, 1);

    if (half == 0) {
        s0 += b2s[0]; s1 += b2s[1]; s2 += b2s[2];
        float sx  = fmaxf(s0, 0.0f) + 1.0f;
        float sy  = fmaxf(s1, 0.0f) + 1.0f;
        float rho = 0.99f * tanhf(s2);
        float sxx = sx * sx;
        float syy = sy * sy;
        float sxy = rho * sx * sy;
        float det = sxx * syy - sxy * sxy;
        float rdet = 1.0f / det;
        // w = -0.5*inv00*dx^2 - inv01*dx*dy - 0.5*inv11*dy^2
        g_coef4[token] = make_float4(-0.5f * syy * rdet, sxy * rdet, -0.5f * sxx * rdet, 0.f);
    }
}

// ---------------------------------------------------------------------------
// Kernel 2: elementwise mask, flat float4 over the whole (bh,i,j) tensor.
// Row-max is exactly 1.0 (PD form => w<=0; CLS col hits w=0 in every row),
// so probs = clip(exp(w), EPS, 1-EPS) with no reduction.
// mask = 1/(1 + r^10), r = (1-p)(1-u)/(p*u).
// ---------------------------------------------------------------------------
__device__ __forceinline__ float mask_lane(float uu, float dx, float dy, float4 c)
{
    const float EPS   = 1e-6f;
    const float OMEPS = 0.999999f;
    float xx = dx * dx, xy = dx * dy, yy = dy * dy;
    float w = fmaf(c.x, xx, fmaf(c.y, xy, c.z * yy));
    float p = __expf(w);
    p = fminf(fmaxf(p, EPS), OMEPS);
    float num = (1.0f - p) * (1.0f - uu);
    float den = p * uu;
    float r   = __fdividef(num, den);
    float r2 = r * r;
    float r4 = r2 * r2;
    float r10 = r4 * r4 * r2;      // inf -> 0 mask; 0 -> 1 mask (matches ref saturation)
    return __fdividef(1.0f, 1.0f + r10);
}

__global__ __launch_bounds__(256) void mask_kernel(
    const float* __restrict__ u,
    const float* __restrict__ dists,
    float* __restrict__ out)
{
    const unsigned idx4 = blockIdx.x * 256u + threadIdx.x;
    if (idx4 >= TOTAL4) return;
    const unsigned e = idx4 * 4u;

    unsigned bh = e / NNU;
    unsigned rem = e - bh * NNU;
    unsigned i = rem / 577u;
    unsigned j = rem - i * 577u;

    const float4 u4 = __ldcs((const float4*)(u + e));
    const float2* __restrict__ d2 = (const float2*)dists;

    float4 res;
    if (j <= 573u) {
        // all 4 lanes in one (bh,i) row: one coef load, contiguous dists
        const float4 c = g_coef4[bh * 577u + i];
        const float2* dp = d2 + (size_t)i * 577u + j;
        float2 d0 = dp[0], d1 = dp[1], d2_ = dp[2], d3 = dp[3];
        res.x = mask_lane(u4.x, d0.x, d0.y, c);
        res.y = mask_lane(u4.y, d1.x, d1.y, c);
        res.z = mask_lane(u4.z, d2_.x, d2_.y, c);
        res.w = mask_lane(u4.w, d3.x, d3.y, c);
    } else {
        // row-crossing vector: per-lane carry
        float rl[4];
        const float ul[4] = {u4.x, u4.y, u4.z, u4.w};
        #pragma unroll
        for (int k = 0; k < 4; k++) {
            unsigned jk = j + k, ik = i, bhk = bh;
            if (jk >= 577u) { jk -= 577u; ik += 1u; if (ik >= 577u) { ik = 0u; bhk += 1u; } }
            const float4 c = g_coef4[bhk * 577u + ik];
            const float2 d = d2[(size_t)ik * 577u + jk];
            rl[k] = mask_lane(ul[k], d.x, d.y, c);
        }
        res = make_float4(rl[0], rl[1], rl[2], rl[3]);
    }
    __stcs((float4*)(out + e), res);
}

extern "C" void kernel_launch(void* const* d_in, const int* in_sizes, int n_in,
                              void* d_out, int out_size)
{
    const float* query = (const float*)d_in[0];
    const float* W1    = (const float*)d_in[1];
    const float* b1    = (const float*)d_in[2];
    const float* W2    = (const float*)d_in[3];
    const float* b2    = (const float*)d_in[4];
    const float* u     = (const float*)d_in[5];
    const float* dists = (const float*)d_in[6];
    float* out = (float*)d_out;

    mlp_kernel<<<(NTOK + 127) / 128, 256>>>(query, W1, b1, W2, b2);

    const unsigned nb = (TOTAL4 + 255u) / 256u;   // 31213
    mask_kernel<<<nb, 256>>>(u, dists, out);
}